// round 16
// baseline (speedup 1.0000x reference)
#include <cuda_runtime.h>
#include <cuda_fp16.h>
#include <math.h>
#include <cstdint>

#define NROWS 8192
#define DIN   1024
#define DHID  4096
#define DOUT  1024

// half ping-pong activation buffers
__device__ __half g_h0[NROWS * DHID];
__device__ __half g_h1[NROWS * DHID];
// fp32 final GEMM output
__device__ float g_y3[NROWS * DOUT];
// fp16 weights
__device__ __half g_w1h[DHID * DIN];
__device__ __half g_w2h[DHID * DHID];
__device__ __half g_w3h[DOUT * DHID];

// ───────────────────────── low-level helpers ─────────────────────────
__device__ __forceinline__ uint32_t smem_u32(const void* p) {
    uint32_t a;
    asm("{ .reg .u64 t; cvta.to.shared.u64 t, %1; cvt.u32.u64 %0, t; }" : "=r"(a) : "l"(p));
    return a;
}
__device__ __forceinline__ void ldsm_x4(uint32_t& r0, uint32_t& r1, uint32_t& r2, uint32_t& r3,
                                        uint32_t addr) {
    asm volatile("ldmatrix.sync.aligned.m8n8.x4.shared.b16 {%0,%1,%2,%3}, [%4];"
                 : "=r"(r0), "=r"(r1), "=r"(r2), "=r"(r3) : "r"(addr));
}
__device__ __forceinline__ void mma_f16(float& d0, float& d1, float& d2, float& d3,
                                        uint32_t a0, uint32_t a1, uint32_t a2, uint32_t a3,
                                        uint32_t b0, uint32_t b1) {
    asm volatile(
        "mma.sync.aligned.m16n8k16.row.col.f32.f16.f16.f32 "
        "{%0,%1,%2,%3}, {%4,%5,%6,%7}, {%8,%9}, {%0,%1,%2,%3};"
        : "+f"(d0), "+f"(d1), "+f"(d2), "+f"(d3)
        : "r"(a0), "r"(a1), "r"(a2), "r"(a3), "r"(b0), "r"(b1));
}
#define CP_ASYNC16(dst, src) \
    asm volatile("cp.async.cg.shared.global [%0], [%1], 16;\n" :: "r"(dst), "l"(src))
#define CP_COMMIT()  asm volatile("cp.async.commit_group;\n" ::: "memory")
#define CP_WAIT1()   asm volatile("cp.async.wait_group 1;\n" ::: "memory")
#define CP_WAIT0()   asm volatile("cp.async.wait_group 0;\n" ::: "memory")

__device__ __forceinline__ uint32_t pack_h2(float a, float b) {
    __half2 h = __floats2half2_rn(a, b);
    return *reinterpret_cast<uint32_t*>(&h);
}

// ───────────────────────── elementwise kernels ─────────────────────────
__device__ __forceinline__ float block_reduce_sum(float v) {
    __shared__ float sh[33];
    int lane = threadIdx.x & 31;
    int wid  = threadIdx.x >> 5;
    #pragma unroll
    for (int o = 16; o > 0; o >>= 1) v += __shfl_down_sync(0xffffffffu, v, o);
    if (lane == 0) sh[wid] = v;
    __syncthreads();
    if (wid == 0) {
        float t = (lane < (int)(blockDim.x >> 5)) ? sh[lane] : 0.0f;
        #pragma unroll
        for (int o = 16; o > 0; o >>= 1) t += __shfl_down_sync(0xffffffffu, t, o);
        if (lane == 0) sh[32] = t;
    }
    __syncthreads();
    return sh[32];
}

// fp32 -> fp16 weight conversion
__global__ __launch_bounds__(256) void w2h_kernel(const float4* __restrict__ in,
                                                  uint2* __restrict__ out, int n4) {
    int i = blockIdx.x * blockDim.x + threadIdx.x;
    if (i < n4) {
        float4 v = in[i];
        uint2 o;
        o.x = pack_h2(v.x, v.y);
        o.y = pack_h2(v.z, v.w);
        out[i] = o;
    }
}

// t = logmap0(x) -> fp16
__global__ __launch_bounds__(256) void prep_kernel(const float* __restrict__ x,
                                                   __half* __restrict__ o) {
    int row = blockIdx.x;
    const float4* xr = reinterpret_cast<const float4*>(x + (size_t)row * DIN);
    uint2* orow = reinterpret_cast<uint2*>(o + (size_t)row * DIN);
    float4 v = xr[threadIdx.x];
    float ss;
    __shared__ float s_x0;
    if (threadIdx.x == 0) {
        s_x0 = v.x;
        ss = v.y * v.y + v.z * v.z + v.w * v.w;
    } else {
        ss = v.x * v.x + v.y * v.y + v.z * v.z + v.w * v.w;
    }
    float tot = block_reduce_sum(ss);
    float ns = fmaxf(sqrtf(tot), 1e-7f);
    float d = acoshf(fmaxf(s_x0, 1.0f + 1e-7f));
    float s = d / ns;
    float a0 = (threadIdx.x == 0) ? 0.0f : v.x * s;
    uint2 w;
    w.x = pack_h2(a0, v.y * s);
    w.y = pack_h2(v.z * s, v.w * s);
    orow[threadIdx.x] = w;
}

// In-place inter-layer collapse on fp16 y (D = DHID = 4096 fixed).
__global__ __launch_bounds__(256) void transform_h(__half* __restrict__ y) {
    int row = blockIdx.x;
    float4* yr = reinterpret_cast<float4*>(y + (size_t)row * DHID);
    float vals[16];
    float ss = 0.0f;
    #pragma unroll
    for (int it = 0; it < 2; it++) {
        float4 raw = yr[threadIdx.x + it * 256];
        const __half2* hp = reinterpret_cast<const __half2*>(&raw);
        #pragma unroll
        for (int j = 0; j < 4; j++) {
            float2 f = __half22float2(hp[j]);
            vals[it * 8 + 2 * j] = f.x;
            vals[it * 8 + 2 * j + 1] = f.y;
        }
    }
    #pragma unroll
    for (int e = 0; e < 16; e++) ss += vals[e] * vals[e];
    if (threadIdx.x == 0) ss -= vals[0] * vals[0];   // exclude time component
    float n = fmaxf(sqrtf(block_reduce_sum(ss)), 1e-7f);
    float f = fminf(n, 10.0f) / n;
    if (threadIdx.x == 0) vals[0] = 0.0f;
    #pragma unroll
    for (int it = 0; it < 2; it++) {
        float4 raw;
        uint32_t* up = reinterpret_cast<uint32_t*>(&raw);
        #pragma unroll
        for (int j = 0; j < 4; j++)
            up[j] = pack_h2(vals[it * 8 + 2 * j] * f, vals[it * 8 + 2 * j + 1] * f);
        yr[threadIdx.x + it * 256] = raw;
    }
}

__global__ __launch_bounds__(256) void final_kernel(const float* __restrict__ y,
                                                    float* __restrict__ o) {
    int row = blockIdx.x;
    const float4* yr = reinterpret_cast<const float4*>(y + (size_t)row * DOUT);
    float4* orow = reinterpret_cast<float4*>(o + (size_t)row * DOUT);
    float4 v = yr[threadIdx.x];
    float ss;
    if (threadIdx.x == 0) ss = v.y * v.y + v.z * v.z + v.w * v.w;
    else                  ss = v.x * v.x + v.y * v.y + v.z * v.z + v.w * v.w;
    float n = fmaxf(sqrtf(block_reduce_sum(ss)), 1e-7f);
    float nc = fminf(n, 10.0f);
    float f = sinhf(nc) / n;
    float4 w;
    w.x = v.x * f; w.y = v.y * f; w.z = v.z * f; w.w = v.w * f;
    if (threadIdx.x == 0) w.x = coshf(nc);
    orow[threadIdx.x] = w;
}

// ───────────────────────── mma.sync fp16 GEMM ─────────────────────────
// C[M,Nn] = A[M,K] @ B[Nn,K]^T + bias.  A,B fp16, C fp32 or fp16.
// CTA 128x256x64, 8 warps, warp tile 64x64 (m16n8k16), 3-stage cp.async,
// one __syncthreads per mainloop iteration, 1 CTA/SM (144 KB SMEM).
// SMEM traffic per 2.1M MACs: STS 48KB + LDSM(A x4, B x2) 128KB = 176KB
// -> 1408 cyc < 2048 cyc tensor time: tensor-limited.

#define BM 128
#define BN 256
#define BK 64
#define NSTAGE 3
#define A_STAGE_BYTES (128 * 128)        // 16 KB
#define B_STAGE_BYTES (256 * 128)        // 32 KB
#define SMEM_TOTAL (NSTAGE * (A_STAGE_BYTES + B_STAGE_BYTES))   // 144 KB

template <typename OutT>
__global__ __launch_bounds__(256, 1) void gemm_mma_f16(const __half* __restrict__ A,
                                                       const __half* __restrict__ B,
                                                       const float* __restrict__ bias,
                                                       OutT* __restrict__ C,
                                                       int M, int Nn, int K) {
    extern __shared__ char smem[];
    const uint32_t sbase = smem_u32(smem);                       // A stages
    const uint32_t sbase_b = sbase + NSTAGE * A_STAGE_BYTES;     // B stages

    const int tid  = threadIdx.x;
    const int wid  = tid >> 5;
    const int lane = tid & 31;
    const int g    = lane >> 2;
    const int q    = lane & 3;

    const int bm = blockIdx.y * BM;
    const int bn = blockIdx.x * BN;
    const int wm = (wid & 1) * 64;    // warp M base
    const int wn = (wid >> 1) * 64;   // warp N base (4 warps across 256)

    const int mat = lane >> 3, r8 = lane & 7;
    // A: 4 m16 tiles
    uint32_t a_rowoff[4], a_xor[4];
    const uint32_t a_chi = (uint32_t)(mat >> 1);
    #pragma unroll
    for (int mt = 0; mt < 4; mt++) {
        int row = wm + mt * 16 + (mat & 1) * 8 + r8;
        a_rowoff[mt] = (uint32_t)row * 128u;
        a_xor[mt] = (uint32_t)(row & 7);
    }
    // B: 4 n16 groups (64 cols)
    uint32_t b_rowoff[4], b_xor[4];
    const uint32_t b_chi = (uint32_t)(mat & 1);
    #pragma unroll
    for (int np = 0; np < 4; np++) {
        int row = wn + np * 16 + (mat >> 1) * 8 + r8;
        b_rowoff[np] = (uint32_t)row * 128u;
        b_xor[np] = (uint32_t)(row & 7);
    }

    float acc[4][8][4];
    #pragma unroll
    for (int i = 0; i < 4; i++)
        #pragma unroll
        for (int j = 0; j < 8; j++)
            #pragma unroll
            for (int r = 0; r < 4; r++) acc[i][j][r] = 0.0f;

    const int NC = K / BK;

    auto load_stage = [&](int c, int s) {
        const __half* Ab = A + (size_t)bm * K + (size_t)c * BK;
        const __half* Bb = B + (size_t)bn * K + (size_t)c * BK;
        const uint32_t ad = sbase + (uint32_t)s * A_STAGE_BYTES;
        const uint32_t bd = sbase_b + (uint32_t)s * B_STAGE_BYTES;
        // A: 128 rows x 8 chunks = 1024 slots
        #pragma unroll
        for (int it = 0; it < 4; it++) {
            int slot = tid + it * 256;
            int r = slot >> 3, c4 = slot & 7;
            uint32_t sw = (uint32_t)(c4 ^ (r & 7)) << 4;
            CP_ASYNC16(ad + (uint32_t)r * 128u + sw, Ab + (size_t)r * K + c4 * 8);
        }
        // B: 256 rows x 8 chunks = 2048 slots
        #pragma unroll
        for (int it = 0; it < 8; it++) {
            int slot = tid + it * 256;
            int r = slot >> 3, c4 = slot & 7;
            uint32_t sw = (uint32_t)(c4 ^ (r & 7)) << 4;
            CP_ASYNC16(bd + (uint32_t)r * 128u + sw, Bb + (size_t)r * K + c4 * 8);
        }
    };

    load_stage(0, 0);
    CP_COMMIT();
    load_stage(1, 1);
    CP_COMMIT();

    int sc = 0, sl = 2;
    for (int c = 0; c < NC; c++) {
        CP_WAIT1();            // stage c landed
        __syncthreads();       // stage being overwritten was consumed at c-1
        if (c + 2 < NC) load_stage(c + 2, sl);
        CP_COMMIT();
        sl = (sl == NSTAGE - 1) ? 0 : sl + 1;

        const uint32_t ast = sbase + (uint32_t)sc * A_STAGE_BYTES;
        const uint32_t bst = sbase_b + (uint32_t)sc * B_STAGE_BYTES;
        sc = (sc == NSTAGE - 1) ? 0 : sc + 1;

        #pragma unroll
        for (int ks = 0; ks < 4; ks++) {
            uint32_t af[4][4];
            #pragma unroll
            for (int mt = 0; mt < 4; mt++) {
                uint32_t addr = ast + a_rowoff[mt] +
                                ((((uint32_t)ks * 2u + a_chi) ^ a_xor[mt]) << 4);
                ldsm_x4(af[mt][0], af[mt][1], af[mt][2], af[mt][3], addr);
            }
            uint32_t bf[8][2];
            #pragma unroll
            for (int np = 0; np < 4; np++) {
                uint32_t addr = bst + b_rowoff[np] +
                                ((((uint32_t)ks * 2u + b_chi) ^ b_xor[np]) << 4);
                ldsm_x4(bf[2 * np][0], bf[2 * np][1], bf[2 * np + 1][0], bf[2 * np + 1][1], addr);
            }
            #pragma unroll
            for (int mt = 0; mt < 4; mt++)
                #pragma unroll
                for (int nt = 0; nt < 8; nt++)
                    mma_f16(acc[mt][nt][0], acc[mt][nt][1], acc[mt][nt][2], acc[mt][nt][3],
                            af[mt][0], af[mt][1], af[mt][2], af[mt][3],
                            bf[nt][0], bf[nt][1]);
        }
    }
    CP_WAIT0();

    // Epilogue
    #pragma unroll
    for (int mt = 0; mt < 4; mt++) {
        const int r0 = bm + wm + mt * 16 + g;
        #pragma unroll
        for (int nt = 0; nt < 8; nt++) {
            const int c0 = bn + wn + nt * 8 + q * 2;
            float2 bv = *reinterpret_cast<const float2*>(bias + c0);
            float v0 = acc[mt][nt][0] + bv.x;
            float v1 = acc[mt][nt][1] + bv.y;
            float v2 = acc[mt][nt][2] + bv.x;
            float v3 = acc[mt][nt][3] + bv.y;
            if constexpr (sizeof(OutT) == 2) {
                *reinterpret_cast<uint32_t*>(&C[(size_t)r0 * Nn + c0]) = pack_h2(v0, v1);
                *reinterpret_cast<uint32_t*>(&C[(size_t)(r0 + 8) * Nn + c0]) = pack_h2(v2, v3);
            } else {
                float2 o0{v0, v1}, o1{v2, v3};
                *reinterpret_cast<float2*>(&C[(size_t)r0 * Nn + c0]) = o0;
                *reinterpret_cast<float2*>(&C[(size_t)(r0 + 8) * Nn + c0]) = o1;
            }
        }
    }
}

// ───────────────────────── launch ─────────────────────────
extern "C" void kernel_launch(void* const* d_in, const int* in_sizes, int n_in,
                              void* d_out, int out_size) {
    const float* x  = (const float*)d_in[0];
    const float* W1 = (const float*)d_in[1];
    const float* b1 = (const float*)d_in[2];
    const float* W2 = (const float*)d_in[3];
    const float* b2 = (const float*)d_in[4];
    const float* W3 = (const float*)d_in[5];
    const float* b3 = (const float*)d_in[6];
    float* out = (float*)d_out;

    __half *h0, *h1, *w1h, *w2h, *w3h;
    float* y3;
    cudaGetSymbolAddress((void**)&h0, g_h0);
    cudaGetSymbolAddress((void**)&h1, g_h1);
    cudaGetSymbolAddress((void**)&y3, g_y3);
    cudaGetSymbolAddress((void**)&w1h, g_w1h);
    cudaGetSymbolAddress((void**)&w2h, g_w2h);
    cudaGetSymbolAddress((void**)&w3h, g_w3h);

    cudaFuncSetAttribute(gemm_mma_f16<__half>, cudaFuncAttributeMaxDynamicSharedMemorySize, SMEM_TOTAL);
    cudaFuncSetAttribute(gemm_mma_f16<float>, cudaFuncAttributeMaxDynamicSharedMemorySize, SMEM_TOTAL);

    // fp16 weight conversion
    w2h_kernel<<<(DHID * DIN / 4 + 255) / 256, 256>>>((const float4*)W1, (uint2*)w1h, DHID * DIN / 4);
    w2h_kernel<<<(DHID * DHID / 4 + 255) / 256, 256>>>((const float4*)W2, (uint2*)w2h, DHID * DHID / 4);
    w2h_kernel<<<(DOUT * DHID / 4 + 255) / 256, 256>>>((const float4*)W3, (uint2*)w3h, DOUT * DHID / 4);

    // t1 = logmap0(x) -> fp16 h0
    prep_kernel<<<NROWS, 256>>>(x, h0);

    // y1 = t1 @ W1^T + b1 -> fp16 h1
    {
        dim3 grid(DHID / BN, NROWS / BM);
        gemm_mma_f16<__half><<<grid, 256, SMEM_TOTAL>>>(h0, w1h, b1, h1, NROWS, DHID, DIN);
    }
    transform_h<<<NROWS, 256>>>(h1);   // in place

    // y2 = t2 @ W2^T + b2 -> fp16 h0
    {
        dim3 grid(DHID / BN, NROWS / BM);
        gemm_mma_f16<__half><<<grid, 256, SMEM_TOTAL>>>(h1, w2h, b2, h0, NROWS, DHID, DHID);
    }
    transform_h<<<NROWS, 256>>>(h0);   // in place

    // y3 = t3 @ W3^T + b3 -> fp32
    {
        dim3 grid(DOUT / BN, NROWS / BM);
        gemm_mma_f16<float><<<grid, 256, SMEM_TOTAL>>>(h0, w3h, b3, y3, NROWS, DOUT, DHID);
    }
    final_kernel<<<NROWS, 256>>>(y3, out);
}

// round 17
// speedup vs baseline: 1.0752x; 1.0752x over previous
#include <cuda_runtime.h>
#include <cuda_fp16.h>
#include <math.h>
#include <cstdint>

#define NROWS 8192
#define DIN   1024
#define DHID  4096
#define DOUT  1024

// half ping-pong activation buffers
__device__ __half g_h0[NROWS * DHID];
__device__ __half g_h1[NROWS * DHID];
// fp32 final GEMM output
__device__ float g_y3[NROWS * DOUT];
// fp16 weights
__device__ __half g_w1h[DHID * DIN];
__device__ __half g_w2h[DHID * DHID];
__device__ __half g_w3h[DOUT * DHID];

// ───────────────────────── low-level helpers ─────────────────────────
__device__ __forceinline__ uint32_t smem_u32(const void* p) {
    uint32_t a;
    asm("{ .reg .u64 t; cvta.to.shared.u64 t, %1; cvt.u32.u64 %0, t; }" : "=r"(a) : "l"(p));
    return a;
}
__device__ __forceinline__ void ldsm_x4(uint32_t& r0, uint32_t& r1, uint32_t& r2, uint32_t& r3,
                                        uint32_t addr) {
    asm volatile("ldmatrix.sync.aligned.m8n8.x4.shared.b16 {%0,%1,%2,%3}, [%4];"
                 : "=r"(r0), "=r"(r1), "=r"(r2), "=r"(r3) : "r"(addr));
}
__device__ __forceinline__ void mma_f16(float& d0, float& d1, float& d2, float& d3,
                                        uint32_t a0, uint32_t a1, uint32_t a2, uint32_t a3,
                                        uint32_t b0, uint32_t b1) {
    asm volatile(
        "mma.sync.aligned.m16n8k16.row.col.f32.f16.f16.f32 "
        "{%0,%1,%2,%3}, {%4,%5,%6,%7}, {%8,%9}, {%0,%1,%2,%3};"
        : "+f"(d0), "+f"(d1), "+f"(d2), "+f"(d3)
        : "r"(a0), "r"(a1), "r"(a2), "r"(a3), "r"(b0), "r"(b1));
}
#define CP_ASYNC16(dst, src) \
    asm volatile("cp.async.cg.shared.global [%0], [%1], 16;\n" :: "r"(dst), "l"(src))
#define CP_COMMIT()  asm volatile("cp.async.commit_group;\n" ::: "memory")
#define CP_WAIT1()   asm volatile("cp.async.wait_group 1;\n" ::: "memory")
#define CP_WAIT0()   asm volatile("cp.async.wait_group 0;\n" ::: "memory")

__device__ __forceinline__ uint32_t pack_h2(float a, float b) {
    __half2 h = __floats2half2_rn(a, b);
    return *reinterpret_cast<uint32_t*>(&h);
}

// ───────────────────────── elementwise kernels ─────────────────────────
__device__ __forceinline__ float block_reduce_sum(float v) {
    __shared__ float sh[33];
    int lane = threadIdx.x & 31;
    int wid  = threadIdx.x >> 5;
    #pragma unroll
    for (int o = 16; o > 0; o >>= 1) v += __shfl_down_sync(0xffffffffu, v, o);
    if (lane == 0) sh[wid] = v;
    __syncthreads();
    if (wid == 0) {
        float t = (lane < (int)(blockDim.x >> 5)) ? sh[lane] : 0.0f;
        #pragma unroll
        for (int o = 16; o > 0; o >>= 1) t += __shfl_down_sync(0xffffffffu, t, o);
        if (lane == 0) sh[32] = t;
    }
    __syncthreads();
    return sh[32];
}

// fp32 -> fp16 weight conversion
__global__ __launch_bounds__(256) void w2h_kernel(const float4* __restrict__ in,
                                                  uint2* __restrict__ out, int n4) {
    int i = blockIdx.x * blockDim.x + threadIdx.x;
    if (i < n4) {
        float4 v = in[i];
        uint2 o;
        o.x = pack_h2(v.x, v.y);
        o.y = pack_h2(v.z, v.w);
        out[i] = o;
    }
}

// t = logmap0(x) -> fp16
__global__ __launch_bounds__(256) void prep_kernel(const float* __restrict__ x,
                                                   __half* __restrict__ o) {
    int row = blockIdx.x;
    const float4* xr = reinterpret_cast<const float4*>(x + (size_t)row * DIN);
    uint2* orow = reinterpret_cast<uint2*>(o + (size_t)row * DIN);
    float4 v = xr[threadIdx.x];
    float ss;
    __shared__ float s_x0;
    if (threadIdx.x == 0) {
        s_x0 = v.x;
        ss = v.y * v.y + v.z * v.z + v.w * v.w;
    } else {
        ss = v.x * v.x + v.y * v.y + v.z * v.z + v.w * v.w;
    }
    float tot = block_reduce_sum(ss);
    float ns = fmaxf(sqrtf(tot), 1e-7f);
    float d = acoshf(fmaxf(s_x0, 1.0f + 1e-7f));
    float s = d / ns;
    float a0 = (threadIdx.x == 0) ? 0.0f : v.x * s;
    uint2 w;
    w.x = pack_h2(a0, v.y * s);
    w.y = pack_h2(v.z * s, v.w * s);
    orow[threadIdx.x] = w;
}

// In-place inter-layer collapse on fp16 y (D = DHID = 4096 fixed).
__global__ __launch_bounds__(256) void transform_h(__half* __restrict__ y) {
    int row = blockIdx.x;
    float4* yr = reinterpret_cast<float4*>(y + (size_t)row * DHID);
    float vals[16];
    float ss = 0.0f;
    #pragma unroll
    for (int it = 0; it < 2; it++) {
        float4 raw = yr[threadIdx.x + it * 256];
        const __half2* hp = reinterpret_cast<const __half2*>(&raw);
        #pragma unroll
        for (int j = 0; j < 4; j++) {
            float2 f = __half22float2(hp[j]);
            vals[it * 8 + 2 * j] = f.x;
            vals[it * 8 + 2 * j + 1] = f.y;
        }
    }
    #pragma unroll
    for (int e = 0; e < 16; e++) ss += vals[e] * vals[e];
    if (threadIdx.x == 0) ss -= vals[0] * vals[0];   // exclude time component
    float n = fmaxf(sqrtf(block_reduce_sum(ss)), 1e-7f);
    float f = fminf(n, 10.0f) / n;
    if (threadIdx.x == 0) vals[0] = 0.0f;
    #pragma unroll
    for (int it = 0; it < 2; it++) {
        float4 raw;
        uint32_t* up = reinterpret_cast<uint32_t*>(&raw);
        #pragma unroll
        for (int j = 0; j < 4; j++)
            up[j] = pack_h2(vals[it * 8 + 2 * j] * f, vals[it * 8 + 2 * j + 1] * f);
        yr[threadIdx.x + it * 256] = raw;
    }
}

__global__ __launch_bounds__(256) void final_kernel(const float* __restrict__ y,
                                                    float* __restrict__ o) {
    int row = blockIdx.x;
    const float4* yr = reinterpret_cast<const float4*>(y + (size_t)row * DOUT);
    float4* orow = reinterpret_cast<float4*>(o + (size_t)row * DOUT);
    float4 v = yr[threadIdx.x];
    float ss;
    if (threadIdx.x == 0) ss = v.y * v.y + v.z * v.z + v.w * v.w;
    else                  ss = v.x * v.x + v.y * v.y + v.z * v.z + v.w * v.w;
    float n = fmaxf(sqrtf(block_reduce_sum(ss)), 1e-7f);
    float nc = fminf(n, 10.0f);
    float f = sinhf(nc) / n;
    float4 w;
    w.x = v.x * f; w.y = v.y * f; w.z = v.z * f; w.w = v.w * f;
    if (threadIdx.x == 0) w.x = coshf(nc);
    orow[threadIdx.x] = w;
}

// ───────────────────────── mma.sync fp16 GEMM ─────────────────────────
// C[M,Nn] = A[M,K] @ B[Nn,K]^T + bias.  A,B fp16, C fp32 or fp16.
// CTA 128x128x64 with 4 warps, warp tile 64x64 (m16n8k16).
// 3-stage cp.async, one __syncthreads per iteration, 2 CTAs/SM (96 KB).
// SMEM traffic per CTA chunk: STS 32KB + LDSM 64KB = 96KB (< tensor time).

#define BM 128
#define BN 128
#define BK 64
#define NTHREADS 128
#define NSTAGE 3
#define STAGE_BYTES (128 * 128)          // 16 KB per tile
#define SMEM_TOTAL (2 * NSTAGE * STAGE_BYTES)   // 96 KB

template <typename OutT>
__global__ __launch_bounds__(NTHREADS, 2) void gemm_mma_f16(const __half* __restrict__ A,
                                                            const __half* __restrict__ B,
                                                            const float* __restrict__ bias,
                                                            OutT* __restrict__ C,
                                                            int M, int Nn, int K) {
    extern __shared__ char smem[];
    const uint32_t sbase = smem_u32(smem);                   // A stages
    const uint32_t sbase_b = sbase + NSTAGE * STAGE_BYTES;   // B stages

    const int tid  = threadIdx.x;
    const int wid  = tid >> 5;
    const int lane = tid & 31;
    const int g    = lane >> 2;
    const int q    = lane & 3;

    const int bm = blockIdx.y * BM;
    const int bn = blockIdx.x * BN;
    const int wm = (wid & 1) * 64;    // warp M base (2 warps)
    const int wn = (wid >> 1) * 64;   // warp N base (2 warps)

    const int mat = lane >> 3, r8 = lane & 7;
    // A: 4 m16 tiles
    uint32_t a_rowoff[4], a_xor[4];
    const uint32_t a_chi = (uint32_t)(mat >> 1);
    #pragma unroll
    for (int mt = 0; mt < 4; mt++) {
        int row = wm + mt * 16 + (mat & 1) * 8 + r8;
        a_rowoff[mt] = (uint32_t)row * 128u;
        a_xor[mt] = (uint32_t)(row & 7);
    }
    // B: 4 n16 groups (64 cols)
    uint32_t b_rowoff[4], b_xor[4];
    const uint32_t b_chi = (uint32_t)(mat & 1);
    #pragma unroll
    for (int np = 0; np < 4; np++) {
        int row = wn + np * 16 + (mat >> 1) * 8 + r8;
        b_rowoff[np] = (uint32_t)row * 128u;
        b_xor[np] = (uint32_t)(row & 7);
    }

    float acc[4][8][4];
    #pragma unroll
    for (int i = 0; i < 4; i++)
        #pragma unroll
        for (int j = 0; j < 8; j++)
            #pragma unroll
            for (int r = 0; r < 4; r++) acc[i][j][r] = 0.0f;

    const int NC = K / BK;

    auto load_stage = [&](int c, int s) {
        const __half* Ab = A + (size_t)bm * K + (size_t)c * BK;
        const __half* Bb = B + (size_t)bn * K + (size_t)c * BK;
        const uint32_t ad = sbase + (uint32_t)s * STAGE_BYTES;
        const uint32_t bd = sbase_b + (uint32_t)s * STAGE_BYTES;
        // A: 128 rows x 8 chunks = 1024 slots, 128 threads -> 8 iters
        #pragma unroll
        for (int it = 0; it < 8; it++) {
            int slot = tid + it * NTHREADS;
            int r = slot >> 3, c4 = slot & 7;
            uint32_t sw = (uint32_t)(c4 ^ (r & 7)) << 4;
            CP_ASYNC16(ad + (uint32_t)r * 128u + sw, Ab + (size_t)r * K + c4 * 8);
        }
        #pragma unroll
        for (int it = 0; it < 8; it++) {
            int slot = tid + it * NTHREADS;
            int r = slot >> 3, c4 = slot & 7;
            uint32_t sw = (uint32_t)(c4 ^ (r & 7)) << 4;
            CP_ASYNC16(bd + (uint32_t)r * 128u + sw, Bb + (size_t)r * K + c4 * 8);
        }
    };

    load_stage(0, 0);
    CP_COMMIT();
    load_stage(1, 1);
    CP_COMMIT();

    int sc = 0, sl = 2;
    for (int c = 0; c < NC; c++) {
        CP_WAIT1();            // stage c landed
        __syncthreads();       // stage being overwritten was consumed at c-1
        if (c + 2 < NC) load_stage(c + 2, sl);
        CP_COMMIT();
        sl = (sl == NSTAGE - 1) ? 0 : sl + 1;

        const uint32_t ast = sbase + (uint32_t)sc * STAGE_BYTES;
        const uint32_t bst = sbase_b + (uint32_t)sc * STAGE_BYTES;
        sc = (sc == NSTAGE - 1) ? 0 : sc + 1;

        #pragma unroll
        for (int ks = 0; ks < 4; ks++) {
            uint32_t af[4][4];
            #pragma unroll
            for (int mt = 0; mt < 4; mt++) {
                uint32_t addr = ast + a_rowoff[mt] +
                                ((((uint32_t)ks * 2u + a_chi) ^ a_xor[mt]) << 4);
                ldsm_x4(af[mt][0], af[mt][1], af[mt][2], af[mt][3], addr);
            }
            uint32_t bf[8][2];
            #pragma unroll
            for (int np = 0; np < 4; np++) {
                uint32_t addr = bst + b_rowoff[np] +
                                ((((uint32_t)ks * 2u + b_chi) ^ b_xor[np]) << 4);
                ldsm_x4(bf[2 * np][0], bf[2 * np][1], bf[2 * np + 1][0], bf[2 * np + 1][1], addr);
            }
            #pragma unroll
            for (int mt = 0; mt < 4; mt++)
                #pragma unroll
                for (int nt = 0; nt < 8; nt++)
                    mma_f16(acc[mt][nt][0], acc[mt][nt][1], acc[mt][nt][2], acc[mt][nt][3],
                            af[mt][0], af[mt][1], af[mt][2], af[mt][3],
                            bf[nt][0], bf[nt][1]);
        }
    }
    CP_WAIT0();

    // Epilogue
    #pragma unroll
    for (int mt = 0; mt < 4; mt++) {
        const int r0 = bm + wm + mt * 16 + g;
        #pragma unroll
        for (int nt = 0; nt < 8; nt++) {
            const int c0 = bn + wn + nt * 8 + q * 2;
            float2 bv = *reinterpret_cast<const float2*>(bias + c0);
            float v0 = acc[mt][nt][0] + bv.x;
            float v1 = acc[mt][nt][1] + bv.y;
            float v2 = acc[mt][nt][2] + bv.x;
            float v3 = acc[mt][nt][3] + bv.y;
            if constexpr (sizeof(OutT) == 2) {
                *reinterpret_cast<uint32_t*>(&C[(size_t)r0 * Nn + c0]) = pack_h2(v0, v1);
                *reinterpret_cast<uint32_t*>(&C[(size_t)(r0 + 8) * Nn + c0]) = pack_h2(v2, v3);
            } else {
                float2 o0{v0, v1}, o1{v2, v3};
                *reinterpret_cast<float2*>(&C[(size_t)r0 * Nn + c0]) = o0;
                *reinterpret_cast<float2*>(&C[(size_t)(r0 + 8) * Nn + c0]) = o1;
            }
        }
    }
}

// ───────────────────────── launch ─────────────────────────
extern "C" void kernel_launch(void* const* d_in, const int* in_sizes, int n_in,
                              void* d_out, int out_size) {
    const float* x  = (const float*)d_in[0];
    const float* W1 = (const float*)d_in[1];
    const float* b1 = (const float*)d_in[2];
    const float* W2 = (const float*)d_in[3];
    const float* b2 = (const float*)d_in[4];
    const float* W3 = (const float*)d_in[5];
    const float* b3 = (const float*)d_in[6];
    float* out = (float*)d_out;

    __half *h0, *h1, *w1h, *w2h, *w3h;
    float* y3;
    cudaGetSymbolAddress((void**)&h0, g_h0);
    cudaGetSymbolAddress((void**)&h1, g_h1);
    cudaGetSymbolAddress((void**)&y3, g_y3);
    cudaGetSymbolAddress((void**)&w1h, g_w1h);
    cudaGetSymbolAddress((void**)&w2h, g_w2h);
    cudaGetSymbolAddress((void**)&w3h, g_w3h);

    cudaFuncSetAttribute(gemm_mma_f16<__half>, cudaFuncAttributeMaxDynamicSharedMemorySize, SMEM_TOTAL);
    cudaFuncSetAttribute(gemm_mma_f16<float>, cudaFuncAttributeMaxDynamicSharedMemorySize, SMEM_TOTAL);

    // fp16 weight conversion
    w2h_kernel<<<(DHID * DIN / 4 + 255) / 256, 256>>>((const float4*)W1, (uint2*)w1h, DHID * DIN / 4);
    w2h_kernel<<<(DHID * DHID / 4 + 255) / 256, 256>>>((const float4*)W2, (uint2*)w2h, DHID * DHID / 4);
    w2h_kernel<<<(DOUT * DHID / 4 + 255) / 256, 256>>>((const float4*)W3, (uint2*)w3h, DOUT * DHID / 4);

    // t1 = logmap0(x) -> fp16 h0
    prep_kernel<<<NROWS, 256>>>(x, h0);

    // y1 = t1 @ W1^T + b1 -> fp16 h1
    {
        dim3 grid(DHID / BN, NROWS / BM);
        gemm_mma_f16<__half><<<grid, NTHREADS, SMEM_TOTAL>>>(h0, w1h, b1, h1, NROWS, DHID, DIN);
    }
    transform_h<<<NROWS, 256>>>(h1);   // in place

    // y2 = t2 @ W2^T + b2 -> fp16 h0
    {
        dim3 grid(DHID / BN, NROWS / BM);
        gemm_mma_f16<__half><<<grid, NTHREADS, SMEM_TOTAL>>>(h1, w2h, b2, h0, NROWS, DHID, DHID);
    }
    transform_h<<<NROWS, 256>>>(h0);   // in place

    // y3 = t3 @ W3^T + b3 -> fp32
    {
        dim3 grid(DOUT / BN, NROWS / BM);
        gemm_mma_f16<float><<<grid, NTHREADS, SMEM_TOTAL>>>(h0, w3h, b3, y3, NROWS, DOUT, DHID);
    }
    final_kernel<<<NROWS, 256>>>(y3, out);
}